// round 3
// baseline (speedup 1.0000x reference)
#include <cuda_runtime.h>
#include <cuda_bf16.h>

// MultiScaleDeformableAttention, fixed shapes:
// B=2, nH=8, D=32, Q=21760, L=4 (128^2,64^2,32^2,16^2), P=4
// value: (B, Len, nH, D) fp32 ; sloc: (B,Q,nH,L,P,2) ; aw: (B,Q,nH,L,P)
// out:   (B, Q, nH*D) fp32
//
// R3 mapping: thread = 8 channels (2 x float4); 4 lanes = 1 head;
// one warp = all 8 heads of one (b,q). Coord/address ALU amortized 8x
// vs R1; corner loads are paired LDG.128.

#define BB   2
#define NH   8
#define QQ   21760
#define LEN  21760
#define ROW4 64                  // 256 floats = 64 float4 per spatial loc
#define NWARPS (BB * QQ)         // 43520: warp == (b,q)

__global__ __launch_bounds__(256)
void msda_kernel(const float4* __restrict__ value4,
                 const float4* __restrict__ sloc4,
                 const float4* __restrict__ aw4,
                 float4* __restrict__ out4)
{
    const int warp = (blockIdx.x * blockDim.x + threadIdx.x) >> 5;
    const int lane = threadIdx.x & 31;
    if (warp >= NWARPS) return;

    const int h   = lane >> 2;        // head 0..7
    const int sub = lane & 3;         // 8-channel slice within head
    const int bq  = warp;             // b*Q + q
    const int b   = (bq >= QQ) ? 1 : 0;
    const int whq = bq * NH + h;

    // Per-head sampling data spread over the 4 lanes of the group:
    // 32 loc floats -> lane r holds float4s 2r, 2r+1 (samples 4r..4r+3)
    // 16 weights    -> lane r holds float4 r        (samples 4r..4r+3)
    const float4 sv0 = __ldg(sloc4 + (size_t)whq * 8 + sub * 2);
    const float4 sv1 = __ldg(sloc4 + (size_t)whq * 8 + sub * 2 + 1);
    const float4 wv  = __ldg(aw4   + (size_t)whq * 4 + sub);

    // Base pointer for this (b, h, channel-octet), float4 units.
    const float4* __restrict__ vb =
        value4 + (size_t)b * LEN * ROW4 + h * 8 + sub * 2;

    float4 accA = make_float4(0.f, 0.f, 0.f, 0.f);
    float4 accB = make_float4(0.f, 0.f, 0.f, 0.f);

    const int Hs[4]     = {128, 64, 32, 16};
    const int starts[4] = {0, 16384, 20480, 21504};

    #pragma unroll
    for (int l = 0; l < 4; ++l) {
        const int   Wl   = Hs[l];
        const int   Hl   = Hs[l];
        const float fW   = (float)Wl;
        const float fH   = (float)Hl;
        const int   base = starts[l] * ROW4;
        const int   rowstride = Wl * ROW4;

        #pragma unroll
        for (int p = 0; p < 4; ++p) {
            const int j   = l * 4 + p;
            const int src = j >> 2;     // lane (within 4) holding sample j
            const int jj  = j & 3;

            float xs, ys, ws;
            if      (jj == 0) { xs = sv0.x; ys = sv0.y; ws = wv.x; }
            else if (jj == 1) { xs = sv0.z; ys = sv0.w; ws = wv.y; }
            else if (jj == 2) { xs = sv1.x; ys = sv1.y; ws = wv.z; }
            else              { xs = sv1.z; ys = sv1.w; ws = wv.w; }

            const float xl = __shfl_sync(0xffffffffu, xs, src, 4);
            const float yl = __shfl_sync(0xffffffffu, ys, src, 4);
            const float w  = __shfl_sync(0xffffffffu, ws, src, 4);

            // pixel coords: x = loc_x*W - 0.5
            const float x = fmaf(xl, fW, -0.5f);
            const float y = fmaf(yl, fH, -0.5f);

            const float x0f = floorf(x);
            const float y0f = floorf(y);
            const int   x0  = (int)x0f;
            const int   y0  = (int)y0f;
            const float lx  = x - x0f;
            const float ly  = y - y0f;
            const float hx  = 1.0f - lx;
            const float hy  = 1.0f - ly;

            const bool vx0 = ((unsigned)x0       < (unsigned)Wl);
            const bool vx1 = ((unsigned)(x0 + 1) < (unsigned)Wl);
            const bool vy0 = ((unsigned)y0       < (unsigned)Hl);
            const bool vy1 = ((unsigned)(y0 + 1) < (unsigned)Hl);

            const float w00 = (vx0 & vy0) ? w * hx * hy : 0.f;
            const float w10 = (vx1 & vy0) ? w * lx * hy : 0.f;
            const float w01 = (vx0 & vy1) ? w * hx * ly : 0.f;
            const float w11 = (vx1 & vy1) ? w * lx * ly : 0.f;

            const int xc0 = min(max(x0,     0), Wl - 1);
            const int xc1 = min(max(x0 + 1, 0), Wl - 1);
            const int yc0 = min(max(y0,     0), Hl - 1);
            const int yc1 = min(max(y0 + 1, 0), Hl - 1);

            const int r0 = base + yc0 * rowstride;
            const int r1 = base + yc1 * rowstride;
            const int c0 = xc0 * ROW4;
            const int c1 = xc1 * ROW4;

            const float4* p00 = vb + r0 + c0;
            const float4* p10 = vb + r0 + c1;
            const float4* p01 = vb + r1 + c0;
            const float4* p11 = vb + r1 + c1;

            const float4 a00 = __ldg(p00);
            const float4 b00 = __ldg(p00 + 1);
            const float4 a10 = __ldg(p10);
            const float4 b10 = __ldg(p10 + 1);
            const float4 a01 = __ldg(p01);
            const float4 b01 = __ldg(p01 + 1);
            const float4 a11 = __ldg(p11);
            const float4 b11 = __ldg(p11 + 1);

            accA.x = fmaf(w00, a00.x, accA.x);
            accA.y = fmaf(w00, a00.y, accA.y);
            accA.z = fmaf(w00, a00.z, accA.z);
            accA.w = fmaf(w00, a00.w, accA.w);
            accB.x = fmaf(w00, b00.x, accB.x);
            accB.y = fmaf(w00, b00.y, accB.y);
            accB.z = fmaf(w00, b00.z, accB.z);
            accB.w = fmaf(w00, b00.w, accB.w);

            accA.x = fmaf(w10, a10.x, accA.x);
            accA.y = fmaf(w10, a10.y, accA.y);
            accA.z = fmaf(w10, a10.z, accA.z);
            accA.w = fmaf(w10, a10.w, accA.w);
            accB.x = fmaf(w10, b10.x, accB.x);
            accB.y = fmaf(w10, b10.y, accB.y);
            accB.z = fmaf(w10, b10.z, accB.z);
            accB.w = fmaf(w10, b10.w, accB.w);

            accA.x = fmaf(w01, a01.x, accA.x);
            accA.y = fmaf(w01, a01.y, accA.y);
            accA.z = fmaf(w01, a01.z, accA.z);
            accA.w = fmaf(w01, a01.w, accA.w);
            accB.x = fmaf(w01, b01.x, accB.x);
            accB.y = fmaf(w01, b01.y, accB.y);
            accB.z = fmaf(w01, b01.z, accB.z);
            accB.w = fmaf(w01, b01.w, accB.w);

            accA.x = fmaf(w11, a11.x, accA.x);
            accA.y = fmaf(w11, a11.y, accA.y);
            accA.z = fmaf(w11, a11.z, accA.z);
            accA.w = fmaf(w11, a11.w, accA.w);
            accB.x = fmaf(w11, b11.x, accB.x);
            accB.y = fmaf(w11, b11.y, accB.y);
            accB.z = fmaf(w11, b11.z, accB.z);
            accB.w = fmaf(w11, b11.w, accB.w);
        }
    }

    // out[b, q, h*32 + sub*8 .. +7] -> float4 indices bq*64 + h*8 + sub*2 (+1)
    float4* o = out4 + (size_t)bq * 64 + h * 8 + sub * 2;
    o[0] = accA;
    o[1] = accB;
}

extern "C" void kernel_launch(void* const* d_in, const int* in_sizes, int n_in,
                              void* d_out, int out_size)
{
    const float4* value4 = (const float4*)d_in[0];
    // d_in[1] (shapes), d_in[2] (level starts): compile-time constants.
    const float4* sloc4  = (const float4*)d_in[3];
    const float4* aw4    = (const float4*)d_in[4];
    float4*       out4   = (float4*)d_out;

    const int threads = 256;                 // 8 warps/block
    const int blocks  = NWARPS / 8;          // 5440
    msda_kernel<<<blocks, threads>>>(value4, sloc4, aw4, out4);
}

// round 4
// speedup vs baseline: 1.1978x; 1.1978x over previous
#include <cuda_runtime.h>
#include <cuda_bf16.h>

// MultiScaleDeformableAttention, fixed shapes:
// B=2, nH=8, D=32, Q=21760, L=4 (128^2,64^2,32^2,16^2), P=4
// value: (B, Len, nH, D) fp32 ; sloc: (B,Q,nH,L,P,2) ; aw: (B,Q,nH,L,P)
// out:   (B, Q, nH*D) fp32
//
// R4: two-phase warp specialization.
//  Phase 1: warp's 64 coord problems (4 heads x 16 samples) spread 1/lane
//           x 2 rounds -> (spatial index, weight) pairs into smem.
//  Phase 2: R2's proven coalesced gather (lane = float4 of channels,
//           8 lanes = head, warp = 4 heads), corner params via broadcast LDS.

#define BB   2
#define NH   8
#define QQ   21760
#define LEN  21760
#define ROW4 64                  // 256 floats = 64 float4 per spatial loc
#define NWARPS (BB * QQ * 2)     // 87040: warp = (b,q,headgroup-of-4)

__global__ __launch_bounds__(256)
void msda_kernel(const float4* __restrict__ value4,
                 const float2* __restrict__ sloc2,
                 const float*  __restrict__ aw,
                 float4* __restrict__ out4)
{
    // [warp-in-block][sample 0..63][corner-pair]:
    // element = uint4{S_even, w_even, S_odd, w_odd}
    __shared__ uint4 sbuf[8][64][2];

    const int wib  = threadIdx.x >> 5;
    const int lane = threadIdx.x & 31;
    const int warp = blockIdx.x * 8 + wib;
    if (warp >= NWARPS) return;

    const int hg = warp & 1;          // head group: heads hg*4 .. hg*4+3
    const int bq = warp >> 1;         // b*Q + q
    const int b  = (bq >= QQ) ? 1 : 0;

    // ---------------- Phase 1: coordinates, 2 samples per lane -------------
    #pragma unroll
    for (int t = 0; t < 2; ++t) {
        const int s = lane + t * 32;      // 0..63
        const int g = s >> 4;             // head within group
        const int j = s & 15;             // sample (level*4 + point)
        const int whq = bq * NH + hg * 4 + g;

        const float2 xy = __ldg(sloc2 + (size_t)whq * 16 + j);
        const float  w  = __ldg(aw    + (size_t)whq * 16 + j);

        const int l  = j >> 2;
        const int Wl = 128 >> l;          // H == W per level
        // level start = (65536 - (65536 >> 2l)) / 3 : {0,16384,20480,21504}
        const int start = (65536 - (65536 >> (2 * l))) / 3;
        const float fW = (float)Wl;

        const float x = fmaf(xy.x, fW, -0.5f);
        const float y = fmaf(xy.y, fW, -0.5f);

        const float x0f = floorf(x);
        const float y0f = floorf(y);
        const int   x0  = (int)x0f;
        const int   y0  = (int)y0f;
        const float lx  = x - x0f;
        const float ly  = y - y0f;
        const float hx  = 1.0f - lx;
        const float hy  = 1.0f - ly;

        const bool vx0 = ((unsigned)x0       < (unsigned)Wl);
        const bool vx1 = ((unsigned)(x0 + 1) < (unsigned)Wl);
        const bool vy0 = ((unsigned)y0       < (unsigned)Wl);
        const bool vy1 = ((unsigned)(y0 + 1) < (unsigned)Wl);

        const float w00 = (vx0 & vy0) ? w * hx * hy : 0.f;
        const float w10 = (vx1 & vy0) ? w * lx * hy : 0.f;
        const float w01 = (vx0 & vy1) ? w * hx * ly : 0.f;
        const float w11 = (vx1 & vy1) ? w * lx * ly : 0.f;

        const int xc0 = min(max(x0,     0), Wl - 1);
        const int xc1 = min(max(x0 + 1, 0), Wl - 1);
        const int yc0 = min(max(y0,     0), Wl - 1);
        const int yc1 = min(max(y0 + 1, 0), Wl - 1);

        const int S00 = start + yc0 * Wl + xc0;   // spatial location index
        const int S10 = start + yc0 * Wl + xc1;
        const int S01 = start + yc1 * Wl + xc0;
        const int S11 = start + yc1 * Wl + xc1;

        sbuf[wib][s][0] = make_uint4((unsigned)S00, __float_as_uint(w00),
                                     (unsigned)S10, __float_as_uint(w10));
        sbuf[wib][s][1] = make_uint4((unsigned)S01, __float_as_uint(w01),
                                     (unsigned)S11, __float_as_uint(w11));
    }
    __syncwarp();

    // ---------------- Phase 2: coalesced gather (R2 mapping) ---------------
    const int g   = lane >> 3;        // head within group
    const int sub = lane & 7;         // float4 (4 channels) within head
    const int h   = hg * 4 + g;

    const float4* __restrict__ vb =
        value4 + (size_t)b * LEN * ROW4 + h * 8 + sub;

    float4 acc = make_float4(0.f, 0.f, 0.f, 0.f);

    #pragma unroll
    for (int j = 0; j < 16; ++j) {
        const uint4 p0 = sbuf[wib][g * 16 + j][0];  // broadcast within group
        const uint4 p1 = sbuf[wib][g * 16 + j][1];

        const float4 v00 = __ldg(vb + (size_t)p0.x * ROW4);
        const float4 v10 = __ldg(vb + (size_t)p0.z * ROW4);
        const float4 v01 = __ldg(vb + (size_t)p1.x * ROW4);
        const float4 v11 = __ldg(vb + (size_t)p1.z * ROW4);

        const float w00 = __uint_as_float(p0.y);
        const float w10 = __uint_as_float(p0.w);
        const float w01 = __uint_as_float(p1.y);
        const float w11 = __uint_as_float(p1.w);

        acc.x = fmaf(w00, v00.x, acc.x);
        acc.y = fmaf(w00, v00.y, acc.y);
        acc.z = fmaf(w00, v00.z, acc.z);
        acc.w = fmaf(w00, v00.w, acc.w);
        acc.x = fmaf(w10, v10.x, acc.x);
        acc.y = fmaf(w10, v10.y, acc.y);
        acc.z = fmaf(w10, v10.z, acc.z);
        acc.w = fmaf(w10, v10.w, acc.w);
        acc.x = fmaf(w01, v01.x, acc.x);
        acc.y = fmaf(w01, v01.y, acc.y);
        acc.z = fmaf(w01, v01.z, acc.z);
        acc.w = fmaf(w01, v01.w, acc.w);
        acc.x = fmaf(w11, v11.x, acc.x);
        acc.y = fmaf(w11, v11.y, acc.y);
        acc.z = fmaf(w11, v11.z, acc.z);
        acc.w = fmaf(w11, v11.w, acc.w);
    }

    // out[b, q, h*32 + sub*4 .. +3] -> float4 index bq*64 + h*8 + sub
    out4[(size_t)bq * 64 + h * 8 + sub] = acc;
}

extern "C" void kernel_launch(void* const* d_in, const int* in_sizes, int n_in,
                              void* d_out, int out_size)
{
    const float4* value4 = (const float4*)d_in[0];
    // d_in[1] (shapes), d_in[2] (level starts): compile-time constants.
    const float2* sloc2  = (const float2*)d_in[3];
    const float*  awp    = (const float*)d_in[4];
    float4*       out4   = (float4*)d_out;

    const int threads = 256;                 // 8 warps/block
    const int blocks  = NWARPS / 8;          // 10880
    msda_kernel<<<blocks, threads>>>(value4, sloc2, awp, out4);
}